// round 16
// baseline (speedup 1.0000x reference)
#include <cuda_runtime.h>
#include <cuda_bf16.h>

// BCELoss(reduce=False) with "correct-side" masking — FINAL (held).
//   y in {0,1}. q = y ? p : 1-p.  loss = (q > 0.5) ? 0 : -max(log q, -100)
// log(1-p) only evaluated when p >= 0.5 -> 1-p exact (Sterbenz), matches
// reference log1p(-p) to fp32 precision. Single MUFU.LG2 per element.
//
// Converged configuration (15 rounds of ncu evidence):
//   - contiguous flat partition: each 512-thread CTA owns 1024 consecutive
//     float4 slots -> best DRAM sector locality (strided-persistent: -4% DRAM%)
//   - 2 float4 slots/thread, 4 front-batched LDG.128 (MLP 4; 8 was neutral)
//   - default cache ops (.cs regressed, .cg neutral)
//   - unguarded hot path (N=2^24 divides exactly; guarded remainder kernel
//     exists for generality but launches 0 blocks here)
// Eight identical-binary runs: kernel 26.53-27.68us, DRAM 75.3-78.7%,
// bench 32.83-33.57us -> environmental (DVFS) scatter, not code. Traffic
// floor closed: all 128MB input must be read, all 64MB output written,
// path irrelevant (LTS cap path-independent). 192MB at the ~6.0-6.2TB/s
// DRAM-controller rate for a 2:1 R:W fp32 stream. Holding.

__device__ __forceinline__ float bce_elem(float p, float y) {
    float q = (y > 0.5f) ? p : (1.0f - p);
    if (q > 0.5f) return 0.0f;
    return -fmaxf(__logf(q), -100.0f);
}

__device__ __forceinline__ float4 bce_vec4(float4 p, float4 y) {
    float4 o;
    o.x = bce_elem(p.x, y.x);
    o.y = bce_elem(p.y, y.y);
    o.z = bce_elem(p.z, y.z);
    o.w = bce_elem(p.w, y.w);
    return o;
}

// Full blocks only: no bounds checks, straight-line code.
__global__ void __launch_bounds__(512)
neo_loss_full(const float4* __restrict__ pred,
              const float4* __restrict__ actual,
              float4* __restrict__ out) {
    int base = blockIdx.x * 1024 + threadIdx.x;
    int i1 = base + 512;
    // 4 front-batched LDG.128 per thread
    float4 p0 = pred[base];
    float4 p1 = pred[i1];
    float4 y0 = actual[base];
    float4 y1 = actual[i1];
    out[base] = bce_vec4(p0, y0);
    out[i1]   = bce_vec4(p1, y1);
}

// Guarded remainder over scalar elements [start, n).
__global__ void neo_loss_rem(const float* __restrict__ pred,
                             const float* __restrict__ actual,
                             float* __restrict__ out,
                             int start, int n) {
    int i = start + blockIdx.x * blockDim.x + threadIdx.x;
    if (i >= n) return;
    out[i] = bce_elem(pred[i], actual[i]);
}

extern "C" void kernel_launch(void* const* d_in, const int* in_sizes, int n_in,
                              void* d_out, int out_size) {
    const float* pred   = (const float*)d_in[0];
    const float* actual = (const float*)d_in[1];
    float* out = (float*)d_out;
    int n = in_sizes[0];

    int n4 = n >> 2;                    // float4 count
    int full_blocks = n4 >> 10;         // 1024 float4 slots per block
    int covered = (full_blocks << 10) << 2;  // elements covered unguarded

    if (full_blocks > 0) {
        neo_loss_full<<<full_blocks, 512>>>(
            (const float4*)pred, (const float4*)actual, (float4*)out);
    }
    if (covered < n) {
        int rem = n - covered;
        neo_loss_rem<<<(rem + 255) / 256, 256>>>(pred, actual, out, covered, n);
    }
}

// round 17
// speedup vs baseline: 1.0185x; 1.0185x over previous
#include <cuda_runtime.h>
#include <cuda_bf16.h>

// BCELoss(reduce=False) with "correct-side" masking — FINAL (held).
//   y in {0,1}. q = y ? p : 1-p.  loss = (q > 0.5) ? 0 : -max(log q, -100)
// log(1-p) only evaluated when p >= 0.5 -> 1-p exact (Sterbenz), matches
// reference log1p(-p) to fp32 precision. Single MUFU.LG2 per element.
//
// Converged configuration (16 rounds of ncu evidence):
//   - contiguous flat partition: each 512-thread CTA owns 1024 consecutive
//     float4 slots -> best DRAM sector locality (strided-persistent: -4% DRAM%)
//   - 2 float4 slots/thread, 4 front-batched LDG.128 (MLP 4; 8 was neutral)
//   - default cache ops (.cs regressed, .cg neutral)
//   - unguarded hot path (N=2^24 divides exactly; guarded remainder kernel
//     exists for generality but launches 0 blocks here)
// Nine identical-binary runs: kernel 26.53-27.68us, DRAM 75.3-78.7%,
// bench 32.83-33.57us -> environmental (DVFS + harness timer) scatter, not
// code. Traffic floor closed: all 128MB input must be read, all 64MB output
// written, path irrelevant (LTS cap path-independent). 192MB at the
// ~6.0-6.2TB/s DRAM-controller rate for a 2:1 R:W fp32 stream. Holding.

__device__ __forceinline__ float bce_elem(float p, float y) {
    float q = (y > 0.5f) ? p : (1.0f - p);
    if (q > 0.5f) return 0.0f;
    return -fmaxf(__logf(q), -100.0f);
}

__device__ __forceinline__ float4 bce_vec4(float4 p, float4 y) {
    float4 o;
    o.x = bce_elem(p.x, y.x);
    o.y = bce_elem(p.y, y.y);
    o.z = bce_elem(p.z, y.z);
    o.w = bce_elem(p.w, y.w);
    return o;
}

// Full blocks only: no bounds checks, straight-line code.
__global__ void __launch_bounds__(512)
neo_loss_full(const float4* __restrict__ pred,
              const float4* __restrict__ actual,
              float4* __restrict__ out) {
    int base = blockIdx.x * 1024 + threadIdx.x;
    int i1 = base + 512;
    // 4 front-batched LDG.128 per thread
    float4 p0 = pred[base];
    float4 p1 = pred[i1];
    float4 y0 = actual[base];
    float4 y1 = actual[i1];
    out[base] = bce_vec4(p0, y0);
    out[i1]   = bce_vec4(p1, y1);
}

// Guarded remainder over scalar elements [start, n).
__global__ void neo_loss_rem(const float* __restrict__ pred,
                             const float* __restrict__ actual,
                             float* __restrict__ out,
                             int start, int n) {
    int i = start + blockIdx.x * blockDim.x + threadIdx.x;
    if (i >= n) return;
    out[i] = bce_elem(pred[i], actual[i]);
}

extern "C" void kernel_launch(void* const* d_in, const int* in_sizes, int n_in,
                              void* d_out, int out_size) {
    const float* pred   = (const float*)d_in[0];
    const float* actual = (const float*)d_in[1];
    float* out = (float*)d_out;
    int n = in_sizes[0];

    int n4 = n >> 2;                    // float4 count
    int full_blocks = n4 >> 10;         // 1024 float4 slots per block
    int covered = (full_blocks << 10) << 2;  // elements covered unguarded

    if (full_blocks > 0) {
        neo_loss_full<<<full_blocks, 512>>>(
            (const float4*)pred, (const float4*)actual, (float4*)out);
    }
    if (covered < n) {
        int rem = n - covered;
        neo_loss_rem<<<(rem + 255) / 256, 256>>>(pred, actual, out, covered, n);
    }
}